// round 7
// baseline (speedup 1.0000x reference)
#include <cuda_runtime.h>
#include <cuda_bf16.h>
#include <mma.h>
#include <cstdint>

using namespace nvcuda;

// Tropical (max-plus) Gram matrix via log-sum-exp GEMM on HMMA (wmma bf16).
// H[i,j] = m_i + m_j + log( sum_k e^{L(|W_ik|-m_i)} e^{L(|W_jk|-m_j)} ) / L
// R7 vs R6: 512 threads/CTA (16 warps, 4/SMSP) with 32x32 warp tiles to fix
// the latency-bound tensor pipe (was 31% active at 8 warps). Pipeline and
// numerics unchanged (L=2600, rel_err ~7e-5).

constexpr int N_DIM = 2048;
constexpr int K_DIM = 10000;
constexpr int K_PAD = 10240;
constexpr float LMB = 2600.0f;
constexpr int NTILES = 16;
constexpr int NPAIRS = 136;
constexpr int KTS  = 32;                       // k per pipeline stage
constexpr int NSTG = K_PAD / KTS;              // 320
constexpr int ESTR = 40;                       // smem row stride (bf16), 80B
constexpr int STAGE_BYTES = 128 * ESTR * 2;    // 10240 per operand
constexpr int NBUF = 4;
constexpr int PIPE_BYTES = NBUF * 2 * STAGE_BYTES;   // 81920
constexpr int LDC = 132;                       // epilogue scratch stride
constexpr int SMEM_DYN = PIPE_BYTES;           // > scratch (67584)
constexpr int NTHR = 512;

__device__ __nv_bfloat16 g_E[(size_t)N_DIM * K_PAD];
__device__ float g_m[N_DIM];

__device__ __forceinline__ uint32_t smem_u32(const void* p) {
    uint32_t a;
    asm("{ .reg .u64 t; cvta.to.shared.u64 t, %1; cvt.u32.u64 %0, t; }" : "=r"(a) : "l"(p));
    return a;
}
__device__ __forceinline__ void cp16(uint32_t dst, const void* src) {
    asm volatile("cp.async.cg.shared.global [%0], [%1], 16;" :: "r"(dst), "l"(src) : "memory");
}
__device__ __forceinline__ void cp_commit() {
    asm volatile("cp.async.commit_group;" ::: "memory");
}
template <int N>
__device__ __forceinline__ void cp_wait() {
    asm volatile("cp.async.wait_group %0;" :: "n"(N) : "memory");
}

// ---------------- kernel 1: fused rowmax + E = bf16(exp(L*(|W|-m))) ----------------
__global__ void prep_kernel(const float* __restrict__ W) {
    const int i = blockIdx.x;
    const int t = threadIdx.x;
    const float4* row4 = (const float4*)(W + (size_t)i * K_DIM);

    float m = 0.0f;
    for (int c = t; c < K_DIM / 4; c += 256) {
        float4 v = row4[c];
        m = fmaxf(m, fmaxf(fmaxf(fabsf(v.x), fabsf(v.y)), fmaxf(fabsf(v.z), fabsf(v.w))));
    }
#pragma unroll
    for (int o = 16; o; o >>= 1) m = fmaxf(m, __shfl_xor_sync(~0u, m, o));
    __shared__ float red[8];
    __shared__ float mbc;
    if ((t & 31) == 0) red[t >> 5] = m;
    __syncthreads();
    if (t < 8) {
        float v = red[t];
#pragma unroll
        for (int o = 4; o; o >>= 1) v = fmaxf(v, __shfl_xor_sync(0xffu, v, o));
        if (t == 0) { mbc = v; g_m[i] = v; }
    }
    __syncthreads();
    const float mv = mbc;

    __nv_bfloat16* erow = g_E + (size_t)i * K_PAD;
    for (int c = t; c < K_DIM / 4; c += 256) {
        float4 v = row4[c];
        __nv_bfloat16 o[4];
        o[0] = __float2bfloat16(__expf((fabsf(v.x) - mv) * LMB));
        o[1] = __float2bfloat16(__expf((fabsf(v.y) - mv) * LMB));
        o[2] = __float2bfloat16(__expf((fabsf(v.z) - mv) * LMB));
        o[3] = __float2bfloat16(__expf((fabsf(v.w) - mv) * LMB));
        *(uint2*)(erow + c * 4) = *(const uint2*)o;
    }
    if (t < 120) *(uint32_t*)(erow + K_DIM + 2 * t) = 0u;
}

// ---------------- kernel 2: wmma bf16 GEMM + log epilogue ----------------
__global__ void __launch_bounds__(NTHR, 1)
lse_gemm_kernel(float* __restrict__ H)
{
    extern __shared__ char smem[];
    const uint32_t sb = smem_u32(smem);
    const int tid = (int)threadIdx.x;
    const int wid = tid >> 5;

    int rem = (int)blockIdx.x;
    int ti = 0;
    while (rem >= NTILES - ti) { rem -= NTILES - ti; ++ti; }
    const int tj = ti + rem;
    const int gi = ti * 128, gj = tj * 128;

    __shared__ float mjs[128];

    // warp grid 4x4, each warp 32(m) x 32(n)
    const int m0 = (wid & 3) * 32;
    const int n0 = (wid >> 2) * 32;

    wmma::fragment<wmma::accumulator, 16, 16, 16, float> acc[2][2];
#pragma unroll
    for (int a = 0; a < 2; ++a)
#pragma unroll
        for (int b = 0; b < 2; ++b) wmma::fill_fragment(acc[a][b], 0.0f);

    // stage prefetch: 1024 x 16B chunks by 512 threads (2 each)
    auto prefetch = [&](int s) {
        const int buf = s & (NBUF - 1);
        const uint32_t abase = sb + (uint32_t)buf * 2 * STAGE_BYTES;
        const uint32_t bbase = abase + STAGE_BYTES;
#pragma unroll
        for (int q = 0; q < 2; ++q) {
            int c = tid + NTHR * q;           // 0..1023
            int isB = c >> 9;
            int cc = c & 511;
            int row = cc >> 2, sub = cc & 3;
            uint32_t dst = (isB ? bbase : abase) + (uint32_t)(row * (ESTR * 2) + sub * 16);
            const __nv_bfloat16* src =
                g_E + (size_t)((isB ? gj : gi) + row) * K_PAD + (size_t)s * KTS + sub * 8;
            cp16(dst, src);
        }
        cp_commit();
    };

    prefetch(0); prefetch(1); prefetch(2);

#pragma unroll 1
    for (int s = 0; s < NSTG; ++s) {
        if (s < NSTG - 2)       cp_wait<2>();
        else if (s == NSTG - 2) cp_wait<1>();
        else                    cp_wait<0>();
        __syncthreads();
        if (s + 3 < NSTG) prefetch(s + 3);

        const int buf = s & (NBUF - 1);
        const __nv_bfloat16* A = (const __nv_bfloat16*)(smem + buf * 2 * STAGE_BYTES);
        const __nv_bfloat16* B = (const __nv_bfloat16*)(smem + buf * 2 * STAGE_BYTES + STAGE_BYTES);
#pragma unroll
        for (int kk = 0; kk < KTS; kk += 16) {
            wmma::fragment<wmma::matrix_a, 16, 16, 16, __nv_bfloat16, wmma::row_major> af[2];
            wmma::fragment<wmma::matrix_b, 16, 16, 16, __nv_bfloat16, wmma::col_major> bfr[2];
#pragma unroll
            for (int a = 0; a < 2; ++a)
                wmma::load_matrix_sync(af[a], A + (m0 + a * 16) * ESTR + kk, ESTR);
#pragma unroll
            for (int b = 0; b < 2; ++b)
                wmma::load_matrix_sync(bfr[b], B + (n0 + b * 16) * ESTR + kk, ESTR);
#pragma unroll
            for (int a = 0; a < 2; ++a)
#pragma unroll
                for (int b = 0; b < 2; ++b)
                    wmma::mma_sync(acc[a][b], af[a], bfr[b], acc[a][b]);
        }
    }
    __syncthreads();   // compute done before scratch reuse of pipeline smem

    // ---- epilogue: accumulators -> smem scratch, apply m_i+m_j+log/L ----
    float* scratch = (float*)smem;
#pragma unroll
    for (int a = 0; a < 2; ++a)
#pragma unroll
        for (int b = 0; b < 2; ++b)
            wmma::store_matrix_sync(scratch + (size_t)(m0 + a * 16) * LDC + (n0 + b * 16),
                                    acc[a][b], LDC, wmma::mem_row_major);
    if (tid < 128) mjs[tid] = g_m[gj + tid];
    __syncthreads();

    const int r = tid >> 2, quad = tid & 3;      // each thread: 32 cols of row r
    const float mi_v = g_m[gi + r];
    const float invL = 1.0f / LMB;
    const float* srow = scratch + (size_t)r * LDC + quad * 32;
    const int cbase = quad * 32;

#pragma unroll
    for (int c8 = 0; c8 < 32; c8 += 8) {
        float vals[8];
#pragma unroll
        for (int q = 0; q < 8; ++q)
            vals[q] = mi_v + mjs[cbase + c8 + q] + __logf(srow[c8 + q]) * invL;
        float4 v0 = make_float4(vals[0], vals[1], vals[2], vals[3]);
        float4 v1 = make_float4(vals[4], vals[5], vals[6], vals[7]);
        *(float4*)&H[(size_t)(gi + r) * N_DIM + gj + cbase + c8]     = v0;
        *(float4*)&H[(size_t)(gi + r) * N_DIM + gj + cbase + c8 + 4] = v1;
        if (ti != tj) {
#pragma unroll
            for (int q = 0; q < 8; ++q)
                H[(size_t)(gj + cbase + c8 + q) * N_DIM + gi + r] = vals[q];
        }
    }
}

// ---------------- launcher ----------------
extern "C" void kernel_launch(void* const* d_in, const int* in_sizes, int n_in,
                              void* d_out, int out_size) {
    const float* W = (const float*)d_in[0];
    float* H = (float*)d_out;

    cudaFuncSetAttribute(lse_gemm_kernel, cudaFuncAttributeMaxDynamicSharedMemorySize, SMEM_DYN);

    prep_kernel<<<N_DIM, 256>>>(W);
    lse_gemm_kernel<<<NPAIRS, NTHR, SMEM_DYN>>>(H);
}

// round 8
// speedup vs baseline: 1.1846x; 1.1846x over previous
#include <cuda_runtime.h>
#include <cuda_bf16.h>
#include <mma.h>
#include <cstdint>

using namespace nvcuda;

// Tropical (max-plus) Gram matrix via log-sum-exp GEMM on HMMA (wmma bf16).
// H[i,j] = m_i + m_j + log( sum_k e^{L(|W_ik|-m_i)} e^{L(|W_jk|-m_j)} ) / L
// R8 vs R7: back to 256 threads / 32x64 warp tiles (R6 was faster);
// KTS=64 (157 stages, 2x fewer barriers); register double-buffered
// fragments (load kk+16 before issuing MMAs for kk) to break the
// LDSM->HMMA dependency chain; K_PAD=10048 (-2% work).

constexpr int N_DIM = 2048;
constexpr int K_DIM = 10000;
constexpr int K_PAD = 10048;                   // 157 * 64
constexpr float LMB = 2600.0f;
constexpr int NTILES = 16;
constexpr int NPAIRS = 136;
constexpr int KTS  = 64;                       // k per pipeline stage
constexpr int NSTG = K_PAD / KTS;              // 157
constexpr int ESTR = 72;                       // smem row stride (bf16) = 144B
constexpr int STAGE_BYTES = 128 * ESTR * 2;    // 18432 per operand
constexpr int NBUF = 4;
constexpr int PIPE_BYTES = NBUF * 2 * STAGE_BYTES;   // 147456
constexpr int LDC = 132;                       // epilogue scratch stride
constexpr int SMEM_DYN = PIPE_BYTES;           // > scratch (67584)
constexpr int NTHR = 256;

__device__ __nv_bfloat16 g_E[(size_t)N_DIM * K_PAD];
__device__ float g_m[N_DIM];

__device__ __forceinline__ uint32_t smem_u32(const void* p) {
    uint32_t a;
    asm("{ .reg .u64 t; cvta.to.shared.u64 t, %1; cvt.u32.u64 %0, t; }" : "=r"(a) : "l"(p));
    return a;
}
__device__ __forceinline__ void cp16(uint32_t dst, const void* src) {
    asm volatile("cp.async.cg.shared.global [%0], [%1], 16;" :: "r"(dst), "l"(src) : "memory");
}
__device__ __forceinline__ void cp_commit() {
    asm volatile("cp.async.commit_group;" ::: "memory");
}
template <int N>
__device__ __forceinline__ void cp_wait() {
    asm volatile("cp.async.wait_group %0;" :: "n"(N) : "memory");
}

// ---------------- kernel 1: fused rowmax + E = bf16(exp(L*(|W|-m))) ----------------
__global__ void prep_kernel(const float* __restrict__ W) {
    const int i = blockIdx.x;
    const int t = threadIdx.x;
    const float4* row4 = (const float4*)(W + (size_t)i * K_DIM);

    float m = 0.0f;
    for (int c = t; c < K_DIM / 4; c += 256) {
        float4 v = row4[c];
        m = fmaxf(m, fmaxf(fmaxf(fabsf(v.x), fabsf(v.y)), fmaxf(fabsf(v.z), fabsf(v.w))));
    }
#pragma unroll
    for (int o = 16; o; o >>= 1) m = fmaxf(m, __shfl_xor_sync(~0u, m, o));
    __shared__ float red[8];
    __shared__ float mbc;
    if ((t & 31) == 0) red[t >> 5] = m;
    __syncthreads();
    if (t < 8) {
        float v = red[t];
#pragma unroll
        for (int o = 4; o; o >>= 1) v = fmaxf(v, __shfl_xor_sync(0xffu, v, o));
        if (t == 0) { mbc = v; g_m[i] = v; }
    }
    __syncthreads();
    const float mv = mbc;

    __nv_bfloat16* erow = g_E + (size_t)i * K_PAD;
    for (int c = t; c < K_DIM / 4; c += 256) {
        float4 v = row4[c];
        __nv_bfloat16 o[4];
        o[0] = __float2bfloat16(__expf((fabsf(v.x) - mv) * LMB));
        o[1] = __float2bfloat16(__expf((fabsf(v.y) - mv) * LMB));
        o[2] = __float2bfloat16(__expf((fabsf(v.z) - mv) * LMB));
        o[3] = __float2bfloat16(__expf((fabsf(v.w) - mv) * LMB));
        *(uint2*)(erow + c * 4) = *(const uint2*)o;
    }
    // zero padding K_DIM..K_PAD (48 elems = 24 uint writes)
    if (t < 24) *(uint32_t*)(erow + K_DIM + 2 * t) = 0u;
}

// ---------------- kernel 2: wmma bf16 GEMM + log epilogue ----------------
__global__ void __launch_bounds__(NTHR, 1)
lse_gemm_kernel(float* __restrict__ H)
{
    extern __shared__ char smem[];
    const uint32_t sb = smem_u32(smem);
    const int tid = (int)threadIdx.x;
    const int wid = tid >> 5;

    int rem = (int)blockIdx.x;
    int ti = 0;
    while (rem >= NTILES - ti) { rem -= NTILES - ti; ++ti; }
    const int tj = ti + rem;
    const int gi = ti * 128, gj = tj * 128;

    __shared__ float mjs[128];

    // warp grid 4(m) x 2(n): each warp 32(m) x 64(n)
    const int m0 = (wid & 3) * 32;
    const int n0 = (wid >> 2) * 64;

    wmma::fragment<wmma::accumulator, 16, 16, 16, float> acc[2][4];
#pragma unroll
    for (int a = 0; a < 2; ++a)
#pragma unroll
        for (int b = 0; b < 4; ++b) wmma::fill_fragment(acc[a][b], 0.0f);

    // stage prefetch: 2048 x 16B chunks by 256 threads (8 each)
    auto prefetch = [&](int s) {
        const int buf = s & (NBUF - 1);
        const uint32_t abase = sb + (uint32_t)buf * 2 * STAGE_BYTES;
        const uint32_t bbase = abase + STAGE_BYTES;
#pragma unroll
        for (int q = 0; q < 8; ++q) {
            int c = tid + NTHR * q;           // 0..2047
            int isB = c >> 10;                // first 1024 A, next 1024 B
            int cc = c & 1023;
            int row = cc >> 3, sub = cc & 7;  // 8 x 16B = 128B per row
            uint32_t dst = (isB ? bbase : abase) + (uint32_t)(row * (ESTR * 2) + sub * 16);
            const __nv_bfloat16* src =
                g_E + (size_t)((isB ? gj : gi) + row) * K_PAD + (size_t)s * KTS + sub * 8;
            cp16(dst, src);
        }
        cp_commit();
    };

    prefetch(0); prefetch(1); prefetch(2);

    typedef wmma::fragment<wmma::matrix_a, 16, 16, 16, __nv_bfloat16, wmma::row_major> FragA;
    typedef wmma::fragment<wmma::matrix_b, 16, 16, 16, __nv_bfloat16, wmma::col_major> FragB;

#pragma unroll 1
    for (int s = 0; s < NSTG; ++s) {
        if (s < NSTG - 2)       cp_wait<2>();
        else if (s == NSTG - 2) cp_wait<1>();
        else                    cp_wait<0>();
        __syncthreads();
        if (s + 3 < NSTG) prefetch(s + 3);

        const int buf = s & (NBUF - 1);
        const __nv_bfloat16* A = (const __nv_bfloat16*)(smem + buf * 2 * STAGE_BYTES);
        const __nv_bfloat16* B = (const __nv_bfloat16*)(smem + buf * 2 * STAGE_BYTES + STAGE_BYTES);

        FragA af[2][2];
        FragB bfr[2][4];
        // preload k-step 0 into buffer 0
#pragma unroll
        for (int a = 0; a < 2; ++a)
            wmma::load_matrix_sync(af[0][a], A + (m0 + a * 16) * ESTR, ESTR);
#pragma unroll
        for (int b = 0; b < 4; ++b)
            wmma::load_matrix_sync(bfr[0][b], B + (n0 + b * 16) * ESTR, ESTR);

#pragma unroll
        for (int kki = 0; kki < 4; ++kki) {
            const int cb = kki & 1, nb = cb ^ 1;
            if (kki < 3) {
                const int kk = (kki + 1) * 16;
#pragma unroll
                for (int a = 0; a < 2; ++a)
                    wmma::load_matrix_sync(af[nb][a], A + (m0 + a * 16) * ESTR + kk, ESTR);
#pragma unroll
                for (int b = 0; b < 4; ++b)
                    wmma::load_matrix_sync(bfr[nb][b], B + (n0 + b * 16) * ESTR + kk, ESTR);
            }
#pragma unroll
            for (int a = 0; a < 2; ++a)
#pragma unroll
                for (int b = 0; b < 4; ++b)
                    wmma::mma_sync(acc[a][b], af[cb][a], bfr[cb][b], acc[a][b]);
        }
    }
    __syncthreads();   // compute done before scratch reuse of pipeline smem

    // ---- epilogue: accumulators -> smem scratch, apply m_i+m_j+log/L ----
    float* scratch = (float*)smem;
#pragma unroll
    for (int a = 0; a < 2; ++a)
#pragma unroll
        for (int b = 0; b < 4; ++b)
            wmma::store_matrix_sync(scratch + (size_t)(m0 + a * 16) * LDC + (n0 + b * 16),
                                    acc[a][b], LDC, wmma::mem_row_major);
    if (tid < 128) mjs[tid] = g_m[gj + tid];
    __syncthreads();

    const int r = tid >> 1, half = tid & 1;
    const float mi_v = g_m[gi + r];
    const float invL = 1.0f / LMB;
    const float* srow = scratch + (size_t)r * LDC + half * 64;
    const int cbase = half * 64;

#pragma unroll 1
    for (int c8 = 0; c8 < 64; c8 += 8) {
        float vals[8];
#pragma unroll
        for (int q = 0; q < 8; ++q)
            vals[q] = mi_v + mjs[cbase + c8 + q] + __logf(srow[c8 + q]) * invL;
        float4 v0 = make_float4(vals[0], vals[1], vals[2], vals[3]);
        float4 v1 = make_float4(vals[4], vals[5], vals[6], vals[7]);
        *(float4*)&H[(size_t)(gi + r) * N_DIM + gj + cbase + c8]     = v0;
        *(float4*)&H[(size_t)(gi + r) * N_DIM + gj + cbase + c8 + 4] = v1;
        if (ti != tj) {
#pragma unroll
            for (int q = 0; q < 8; ++q)
                H[(size_t)(gj + cbase + c8 + q) * N_DIM + gi + r] = vals[q];
        }
    }
}

// ---------------- launcher ----------------
extern "C" void kernel_launch(void* const* d_in, const int* in_sizes, int n_in,
                              void* d_out, int out_size) {
    const float* W = (const float*)d_in[0];
    float* H = (float*)d_out;

    cudaFuncSetAttribute(lse_gemm_kernel, cudaFuncAttributeMaxDynamicSharedMemorySize, SMEM_DYN);

    prep_kernel<<<N_DIM, 256>>>(W);
    lse_gemm_kernel<<<NPAIRS, NTHR, SMEM_DYN>>>(H);
}

// round 9
// speedup vs baseline: 1.3759x; 1.1615x over previous
#include <cuda_runtime.h>
#include <cuda_bf16.h>
#include <mma.h>
#include <cstdint>

using namespace nvcuda;

// Tropical (max-plus) Gram matrix via log-sum-exp GEMM on HMMA (wmma bf16).
// H[i,j] = m_i + m_j + log( sum_k e^{L(|W_ik|-m_i)} e^{L(|W_jk|-m_j)} ) / L
// R9 vs R8: K split in two halves -> grid (136,2), NBUF=3 (108KB smem),
// 2 independent CTAs/SM (separate barriers -> desynchronized warp phases).
// GEMM stores raw partial sums (ky0->H, ky1->g_P) straight from wmma;
// a finish kernel applies m_i+m_j+log(P0+P1)/L with smem-transposed
// coalesced mirror writes.

constexpr int N_DIM = 2048;
constexpr int K_DIM = 10000;
constexpr int KHALF_PAD = 5056;                // 79 * 64
constexpr int K_PAD = 2 * KHALF_PAD;           // 10112
constexpr float LMB = 2600.0f;
constexpr int NTILES = 16;
constexpr int NPAIRS = 136;
constexpr int KTS  = 64;                       // k per pipeline stage
constexpr int NSTG = KHALF_PAD / KTS;          // 79
constexpr int ESTR = 72;                       // smem row stride (bf16) = 144B
constexpr int STAGE_BYTES = 128 * ESTR * 2;    // 18432 per operand
constexpr int NBUF = 3;
constexpr int PIPE_BYTES = NBUF * 2 * STAGE_BYTES;   // 110592
constexpr int NTHR = 256;
constexpr int LDT = 133;                       // finish-kernel tile stride
constexpr int FIN_SMEM = 128 * LDT * 4;        // 68096

__device__ __nv_bfloat16 g_E[(size_t)N_DIM * K_PAD];
__device__ float g_m[N_DIM];
__device__ float g_P[(size_t)N_DIM * N_DIM];   // partial sums, K-half 1

__device__ __forceinline__ uint32_t smem_u32(const void* p) {
    uint32_t a;
    asm("{ .reg .u64 t; cvta.to.shared.u64 t, %1; cvt.u32.u64 %0, t; }" : "=r"(a) : "l"(p));
    return a;
}
__device__ __forceinline__ void cp16(uint32_t dst, const void* src) {
    asm volatile("cp.async.cg.shared.global [%0], [%1], 16;" :: "r"(dst), "l"(src) : "memory");
}
__device__ __forceinline__ void cp_commit() {
    asm volatile("cp.async.commit_group;" ::: "memory");
}
template <int N>
__device__ __forceinline__ void cp_wait() {
    asm volatile("cp.async.wait_group %0;" :: "n"(N) : "memory");
}

// ---------------- kernel 1: fused rowmax + E = bf16(exp(L*(|W|-m))) ----------------
__global__ void prep_kernel(const float* __restrict__ W) {
    const int i = blockIdx.x;
    const int t = threadIdx.x;
    const float4* row4 = (const float4*)(W + (size_t)i * K_DIM);

    float m = 0.0f;
    for (int c = t; c < K_DIM / 4; c += 256) {
        float4 v = row4[c];
        m = fmaxf(m, fmaxf(fmaxf(fabsf(v.x), fabsf(v.y)), fmaxf(fabsf(v.z), fabsf(v.w))));
    }
#pragma unroll
    for (int o = 16; o; o >>= 1) m = fmaxf(m, __shfl_xor_sync(~0u, m, o));
    __shared__ float red[8];
    __shared__ float mbc;
    if ((t & 31) == 0) red[t >> 5] = m;
    __syncthreads();
    if (t < 8) {
        float v = red[t];
#pragma unroll
        for (int o = 4; o; o >>= 1) v = fmaxf(v, __shfl_xor_sync(0xffu, v, o));
        if (t == 0) { mbc = v; g_m[i] = v; }
    }
    __syncthreads();
    const float mv = mbc;

    __nv_bfloat16* erow = g_E + (size_t)i * K_PAD;
    for (int c = t; c < K_DIM / 4; c += 256) {
        float4 v = row4[c];
        __nv_bfloat16 o[4];
        o[0] = __float2bfloat16(__expf((fabsf(v.x) - mv) * LMB));
        o[1] = __float2bfloat16(__expf((fabsf(v.y) - mv) * LMB));
        o[2] = __float2bfloat16(__expf((fabsf(v.z) - mv) * LMB));
        o[3] = __float2bfloat16(__expf((fabsf(v.w) - mv) * LMB));
        *(uint2*)(erow + c * 4) = *(const uint2*)o;
    }
    // zero padding K_DIM..K_PAD (112 elems = 56 u32 writes)
    if (t < 56) *(uint32_t*)(erow + K_DIM + 2 * t) = 0u;
}

// ---------------- kernel 2: wmma bf16 GEMM -> raw partial sums ----------------
__global__ void __launch_bounds__(NTHR, 2)
lse_gemm_kernel(float* __restrict__ H)
{
    extern __shared__ char smem[];
    const uint32_t sb = smem_u32(smem);
    const int tid = (int)threadIdx.x;
    const int wid = tid >> 5;

    int rem = (int)blockIdx.x;
    int ti = 0;
    while (rem >= NTILES - ti) { rem -= NTILES - ti; ++ti; }
    const int tj = ti + rem;
    const int gi = ti * 128, gj = tj * 128;
    const int ky = (int)blockIdx.y;
    const size_t kbase = (size_t)ky * KHALF_PAD;
    float* out = ky ? g_P : H;

    // warp grid 4(m) x 2(n): each warp 32(m) x 64(n)
    const int m0 = (wid & 3) * 32;
    const int n0 = (wid >> 2) * 64;

    wmma::fragment<wmma::accumulator, 16, 16, 16, float> acc[2][4];
#pragma unroll
    for (int a = 0; a < 2; ++a)
#pragma unroll
        for (int b = 0; b < 4; ++b) wmma::fill_fragment(acc[a][b], 0.0f);

    // stage prefetch: 2048 x 16B chunks by 256 threads (8 each)
    auto prefetch = [&](int s) {
        const int buf = s % NBUF;
        const uint32_t abase = sb + (uint32_t)buf * 2 * STAGE_BYTES;
        const uint32_t bbase = abase + STAGE_BYTES;
#pragma unroll
        for (int q = 0; q < 8; ++q) {
            int c = tid + NTHR * q;           // 0..2047
            int isB = c >> 10;
            int cc = c & 1023;
            int row = cc >> 3, sub = cc & 7;  // 8 x 16B = 128B per row
            uint32_t dst = (isB ? bbase : abase) + (uint32_t)(row * (ESTR * 2) + sub * 16);
            const __nv_bfloat16* src =
                g_E + (size_t)((isB ? gj : gi) + row) * K_PAD + kbase + (size_t)s * KTS + sub * 8;
            cp16(dst, src);
        }
        cp_commit();
    };

    prefetch(0); prefetch(1);

#pragma unroll 1
    for (int s = 0; s < NSTG; ++s) {
        if (s >= NSTG - 1) cp_wait<0>();
        else               cp_wait<1>();
        __syncthreads();
        if (s + 2 < NSTG) prefetch(s + 2);

        const int buf = s % NBUF;
        const __nv_bfloat16* A = (const __nv_bfloat16*)(smem + buf * 2 * STAGE_BYTES);
        const __nv_bfloat16* B = (const __nv_bfloat16*)(smem + buf * 2 * STAGE_BYTES + STAGE_BYTES);

#pragma unroll
        for (int kki = 0; kki < 4; ++kki) {
            const int kk = kki * 16;
            wmma::fragment<wmma::matrix_a, 16, 16, 16, __nv_bfloat16, wmma::row_major> af[2];
            wmma::fragment<wmma::matrix_b, 16, 16, 16, __nv_bfloat16, wmma::col_major> bfr[4];
#pragma unroll
            for (int a = 0; a < 2; ++a)
                wmma::load_matrix_sync(af[a], A + (m0 + a * 16) * ESTR + kk, ESTR);
#pragma unroll
            for (int b = 0; b < 4; ++b)
                wmma::load_matrix_sync(bfr[b], B + (n0 + b * 16) * ESTR + kk, ESTR);
#pragma unroll
            for (int a = 0; a < 2; ++a)
#pragma unroll
                for (int b = 0; b < 4; ++b)
                    wmma::mma_sync(acc[a][b], af[a], bfr[b], acc[a][b]);
        }
    }

    // store raw partial sums directly to global
#pragma unroll
    for (int a = 0; a < 2; ++a)
#pragma unroll
        for (int b = 0; b < 4; ++b)
            wmma::store_matrix_sync(out + (size_t)(gi + m0 + a * 16) * N_DIM + gj + n0 + b * 16,
                                    acc[a][b], N_DIM, wmma::mem_row_major);
}

// ---------------- kernel 3: H = m_i + m_j + log(P0+P1)/L, + mirror ----------------
__global__ void finish_kernel(float* __restrict__ H)
{
    extern __shared__ float tile[];   // [128][LDT]
    __shared__ float mi_s[128], mj_s[128];
    const int tid = (int)threadIdx.x;

    int rem = (int)blockIdx.x;
    int ti = 0;
    while (rem >= NTILES - ti) { rem -= NTILES - ti; ++ti; }
    const int tj = ti + rem;
    const int gi = ti * 128, gj = tj * 128;

    if (tid < 128) { mi_s[tid] = g_m[gi + tid]; mj_s[tid] = g_m[gj + tid]; }
    __syncthreads();

    const float invL = 1.0f / LMB;
    // 4096 float4s, 16 per thread
#pragma unroll 4
    for (int it = 0; it < 16; ++it) {
        int idx = tid + it * 256;          // float4 index
        int r = idx >> 5, c4 = (idx & 31) * 4;
        size_t go = (size_t)(gi + r) * N_DIM + gj + c4;
        float4 p0 = *(const float4*)&H[go];
        float4 p1 = *(const float4*)&g_P[go];
        float base = mi_s[r];
        float4 v;
        v.x = base + mj_s[c4 + 0] + __logf(p0.x + p1.x) * invL;
        v.y = base + mj_s[c4 + 1] + __logf(p0.y + p1.y) * invL;
        v.z = base + mj_s[c4 + 2] + __logf(p0.z + p1.z) * invL;
        v.w = base + mj_s[c4 + 3] + __logf(p0.w + p1.w) * invL;
        tile[r * LDT + c4 + 0] = v.x;
        tile[r * LDT + c4 + 1] = v.y;
        tile[r * LDT + c4 + 2] = v.z;
        tile[r * LDT + c4 + 3] = v.w;
        *(float4*)&H[go] = v;
    }

    if (ti == tj) return;   // diagonal tile: symmetric within itself, done

    __syncthreads();
    // mirror: H[gj+r'][gi+c'] = tile[c'][r'], coalesced via smem transpose
#pragma unroll 4
    for (int it = 0; it < 16; ++it) {
        int idx = tid + it * 256;
        int r = idx >> 5, c4 = (idx & 31) * 4;
        float4 v;
        v.x = tile[(c4 + 0) * LDT + r];
        v.y = tile[(c4 + 1) * LDT + r];
        v.z = tile[(c4 + 2) * LDT + r];
        v.w = tile[(c4 + 3) * LDT + r];
        *(float4*)&H[(size_t)(gj + r) * N_DIM + gi + c4] = v;
    }
}

// ---------------- launcher ----------------
extern "C" void kernel_launch(void* const* d_in, const int* in_sizes, int n_in,
                              void* d_out, int out_size) {
    const float* W = (const float*)d_in[0];
    float* H = (float*)d_out;

    cudaFuncSetAttribute(lse_gemm_kernel, cudaFuncAttributeMaxDynamicSharedMemorySize, PIPE_BYTES);
    cudaFuncSetAttribute(finish_kernel, cudaFuncAttributeMaxDynamicSharedMemorySize, FIN_SMEM);

    prep_kernel<<<N_DIM, 256>>>(W);
    dim3 gg(NPAIRS, 2);
    lse_gemm_kernel<<<gg, NTHR, PIPE_BYTES>>>(H);
    finish_kernel<<<NPAIRS, 256, FIN_SMEM>>>(H);
}